// round 1
// baseline (speedup 1.0000x reference)
#include <cuda_runtime.h>
#include <stdint.h>

#define BATCH  8
#define NANCH  100800
#define KPRE   1024
#define MAXDET 100

// ---------------- scratch (static device memory; no runtime allocation) ------
__device__ unsigned int  g_ukey[BATCH][NANCH];
__device__ unsigned char g_cls [BATCH][NANCH];
__device__ float         g_box [BATCH][KPRE][4];   // raw xyxy (output boxes)
__device__ float         g_boff[BATCH][KPRE][4];   // class-offset boxes (IoU)
__device__ float         g_area[BATCH][KPRE];
__device__ float         g_sc  [BATCH][KPRE];      // masked score (sorted desc)
__device__ float         g_cf  [BATCH][KPRE];      // class as float
__device__ unsigned int  g_mask[BATCH][KPRE][32];  // suppression bits (j < i)

// ---------------- kernel 1: score / argmax / sortable key --------------------
__global__ void k_score(const float* __restrict__ pred, int N)
{
    int n = blockIdx.x * blockDim.x + threadIdx.x;
    int b = blockIdx.y;
    if (n >= N) return;
    const float* p = pred + ((size_t)b * N + n) * 85;
    float obj = __ldg(p + 4);
    float best = __fmul_rn(__ldg(p + 5), obj);
    int   bi   = 0;
#pragma unroll 16
    for (int c = 1; c < 80; ++c) {
        float v = __fmul_rn(__ldg(p + 5 + c), obj);
        if (v > best) { best = v; bi = c; }   // strict > == first-occurrence argmax
    }
    bool  valid = (obj > 0.25f) && (best > 0.25f);
    float sm    = valid ? best : -1.0f;
    int   sb    = __float_as_int(sm);
    unsigned u  = (unsigned)sb ^ ((sb < 0) ? 0xFFFFFFFFu : 0x80000000u);
    g_ukey[b][n] = u;
    g_cls [b][n] = (unsigned char)bi;
}

// ---------------- kernel 2: exact top-1024 (radix select) + sort + gather ----
__device__ __forceinline__ void hist_add(unsigned* hist, unsigned bin, bool q)
{
    unsigned qm = __ballot_sync(0xFFFFFFFFu, q);
    if (q) {
        unsigned peers = __match_any_sync(qm, bin);
        int ld = __ffs(peers) - 1;
        if ((int)(threadIdx.x & 31) == ld) atomicAdd(&hist[bin], (unsigned)__popc(peers));
    }
}

__device__ __forceinline__ void find_bin(unsigned* hist, unsigned* chunkSum,
                                         int NB, unsigned K, unsigned* sres, int tid)
{
    int nch = NB >> 5;
    if (tid < nch) {
        unsigned s = 0;
        int base = tid << 5;
#pragma unroll 8
        for (int i = 0; i < 32; ++i) s += hist[base + i];
        chunkSum[tid] = s;
    }
    __syncthreads();
    if (tid == 0) {
        unsigned acc = 0;
        int c = nch - 1;
        for (;; --c) {
            unsigned cs = chunkSum[c];
            if (acc + cs >= K) break;
            acc += cs;
        }
        int bin = (c << 5) + 31;
        for (;; --bin) {
            unsigned hv = hist[bin];
            if (acc + hv >= K) break;
            acc += hv;
        }
        sres[0] = (unsigned)bin;
        sres[1] = acc;           // count strictly above bin
    }
    __syncthreads();
}

__global__ void __launch_bounds__(1024) k_select(const float* __restrict__ pred, int N)
{
    __shared__ unsigned hist[2048];
    __shared__ unsigned chunkSum[64];
    __shared__ unsigned sres[2];
    __shared__ unsigned long long selKey[KPRE];
    __shared__ int eqIdx[2048];
    __shared__ int s_cntGt, s_cntEq;

    int b = blockIdx.x, tid = threadIdx.x;
    const unsigned* uk = &g_ukey[b][0];

    // ---- pass A: top 11 bits ----
    hist[tid] = 0; hist[tid + 1024] = 0;
    __syncthreads();
    for (int n0 = 0; n0 < N; n0 += 1024) {
        int n = n0 + tid; bool act = n < N;
        unsigned u = act ? uk[n] : 0u;
        hist_add(hist, u >> 21, act);
    }
    __syncthreads();
    find_bin(hist, chunkSum, 2048, KPRE, sres, tid);
    unsigned b1 = sres[0], gt1 = sres[1], K1 = KPRE - gt1;
    __syncthreads();

    // ---- pass B: mid 11 bits ----
    hist[tid] = 0; hist[tid + 1024] = 0;
    __syncthreads();
    for (int n0 = 0; n0 < N; n0 += 1024) {
        int n = n0 + tid; bool act = n < N;
        unsigned u = act ? uk[n] : 0u;
        hist_add(hist, (u >> 10) & 2047u, act && ((u >> 21) == b1));
    }
    __syncthreads();
    find_bin(hist, chunkSum, 2048, K1, sres, tid);
    unsigned b2 = sres[0], gt2 = sres[1], K2 = K1 - gt2;
    unsigned pref = (b1 << 11) | b2;
    __syncthreads();

    // ---- pass C: low 10 bits ----
    hist[tid] = 0;
    __syncthreads();
    for (int n0 = 0; n0 < N; n0 += 1024) {
        int n = n0 + tid; bool act = n < N;
        unsigned u = act ? uk[n] : 0u;
        hist_add(hist, u & 1023u, act && ((u >> 10) == pref));
    }
    __syncthreads();
    find_bin(hist, chunkSum, 1024, K2, sres, tid);
    unsigned b3 = sres[0], gt3 = sres[1], K3 = K2 - gt3;  // # elems == pivot to take
    unsigned ustar = (b1 << 21) | (b2 << 10) | b3;
    int totalGt = (int)(KPRE - K3);

    if (tid == 0) { s_cntGt = 0; s_cntEq = 0; }
    __syncthreads();

    // ---- pass D: compact ----
    for (int n = tid; n < N; n += 1024) {
        unsigned u = uk[n];
        if (u > ustar) {
            int p = atomicAdd(&s_cntGt, 1);
            selKey[p] = ((unsigned long long)u << 32) | (unsigned)(~n);
        } else if (u == ustar) {
            int q = atomicAdd(&s_cntEq, 1);
            if (q < 2048) eqIdx[q] = n;
        }
    }
    __syncthreads();

    // ---- pass E: tie resolution by smallest index (jax top_k semantics) ----
    int E = s_cntEq; if (E > 2048) E = 2048;
    for (int t = tid; t < E; t += 1024) {
        int my = eqIdx[t], r = 0;
        for (int s = 0; s < E; ++s) r += (eqIdx[s] < my);
        if (r < (int)K3)
            selKey[totalGt + r] = ((unsigned long long)ustar << 32) | (unsigned)(~my);
    }
    __syncthreads();

    // ---- bitonic sort descending (ties -> smaller index first via ~n) ----
    for (int k = 2; k <= KPRE; k <<= 1) {
        for (int j = k >> 1; j > 0; j >>= 1) {
            int ixj = tid ^ j;
            if (ixj > tid) {
                unsigned long long a = selKey[tid], c2 = selKey[ixj];
                bool desc = ((tid & k) == 0);
                if (desc ? (a < c2) : (a > c2)) { selKey[tid] = c2; selKey[ixj] = a; }
            }
            __syncthreads();
        }
    }

    // ---- gather boxes / class / score (bit-exact reference arithmetic) ----
    {
        unsigned long long key = selKey[tid];
        unsigned n = ~((unsigned)(key & 0xFFFFFFFFull));
        unsigned u = (unsigned)(key >> 32);
        unsigned sb = (u & 0x80000000u) ? (u ^ 0x80000000u) : ~u;
        float sc = __int_as_float((int)sb);
        const float* p = pred + ((size_t)b * N + n) * 85;
        float cx = __ldg(p), cy = __ldg(p + 1), w = __ldg(p + 2), h = __ldg(p + 3);
        float hw = __fmul_rn(w, 0.5f), hh = __fmul_rn(h, 0.5f);
        float x1 = __fsub_rn(cx, hw), y1 = __fsub_rn(cy, hh);
        float x2 = __fadd_rn(cx, hw), y2 = __fadd_rn(cy, hh);
        float cf = (float)(int)g_cls[b][n];
        float off = __fmul_rn(cf, 7680.0f);
        float o0 = __fadd_rn(x1, off), o1 = __fadd_rn(y1, off);
        float o2 = __fadd_rn(x2, off), o3 = __fadd_rn(y2, off);
        g_box [b][tid][0] = x1; g_box [b][tid][1] = y1;
        g_box [b][tid][2] = x2; g_box [b][tid][3] = y2;
        g_boff[b][tid][0] = o0; g_boff[b][tid][1] = o1;
        g_boff[b][tid][2] = o2; g_boff[b][tid][3] = o3;
        g_area[b][tid] = __fmul_rn(__fsub_rn(o2, o0), __fsub_rn(o3, o1));
        g_sc  [b][tid] = sc;
        g_cf  [b][tid] = cf;
    }
}

// ---------------- kernel 3a: suppression bitmask matrix -----------------------
__global__ void __launch_bounds__(256) k_mask()
{
    __shared__ float sb0[KPRE], sb1[KPRE], sb2[KPRE], sb3[KPRE], sar[KPRE];
    int b = blockIdx.x >> 2;
    int chunk = blockIdx.x & 3;
    for (int i = threadIdx.x; i < KPRE; i += 256) {
        sb0[i] = g_boff[b][i][0];
        sb1[i] = g_boff[b][i][1];
        sb2[i] = g_boff[b][i][2];
        sb3[i] = g_boff[b][i][3];
        sar[i] = g_area[b][i];
    }
    __syncthreads();
    int i = (chunk << 8) + threadIdx.x;
    float a0 = sb0[i], a1 = sb1[i], a2 = sb2[i], a3 = sb3[i], aa = sar[i];
    for (int w = 0; w < 32; ++w) {
        unsigned m = 0;
        int base = w << 5;
        int lim = i - base; if (lim > 32) lim = 32;
        for (int jj = 0; jj < lim; ++jj) {
            int j = base + jj;
            float xx1 = fmaxf(a0, sb0[j]);
            float yy1 = fmaxf(a1, sb1[j]);
            float xx2 = fminf(a2, sb2[j]);
            float yy2 = fminf(a3, sb3[j]);
            float ww = fmaxf(__fsub_rn(xx2, xx1), 0.0f);
            float hh = fmaxf(__fsub_rn(yy2, yy1), 0.0f);
            float inter = __fmul_rn(ww, hh);
            float uni = __fsub_rn(__fadd_rn(aa, sar[j]), inter);
            float iou = __fdiv_rn(inter, __fadd_rn(uni, 1e-7f));
            if (iou > 0.45f) m |= (1u << jj);
        }
        g_mask[b][i][w] = m;
    }
}

// ---------------- kernel 3b: serial greedy scan (1 warp / batch) --------------
__global__ void __launch_bounds__(32) k_scan(float* __restrict__ out)
{
    __shared__ int list[MAXDET];
    int b = blockIdx.x;
    int l = threadIdx.x;

    // valid count V (scores sorted desc, so valid == prefix)
    int cnt = 0;
    const float* sc = &g_sc[b][0];
    for (int j = 0; j < 32; ++j) cnt += (sc[(l << 5) + j] > 0.0f) ? 1 : 0;
    for (int o = 16; o; o >>= 1) cnt += __shfl_xor_sync(0xFFFFFFFFu, cnt, o);
    int V = cnt;

    unsigned kept = 0;
    int kc = 0;
    const unsigned* mrow = &g_mask[b][0][0];
    unsigned mA[8], mB[8];
#pragma unroll
    for (int k = 0; k < 8; ++k) mA[k] = mrow[(k << 5) + l];

    for (int base = 0; base < KPRE; base += 8) {
#pragma unroll
        for (int k = 0; k < 8; ++k) {
            int r = base + 8 + k;
            mB[k] = (r < KPRE) ? mrow[(r << 5) + l] : 0u;
        }
#pragma unroll
        for (int k = 0; k < 8; ++k) {
            int i = base + k;
            bool hit = (mA[k] & kept) != 0u;
            unsigned bal = __ballot_sync(0xFFFFFFFFu, hit);
            if (i < V && bal == 0u) {
                if (l == (i >> 5)) kept |= 1u << (i & 31);
                if (l == 0 && kc < MAXDET) list[kc] = i;
                kc++;
            }
        }
        if (kc >= MAXDET) break;   // only first 100 kept are observable
#pragma unroll
        for (int k = 0; k < 8; ++k) mA[k] = mB[k];
    }
    __syncwarp();

    int K = kc < MAXDET ? kc : MAXDET;
    for (int s = l; s < K; s += 32) {
        int i = list[s];
        float* o = out + ((size_t)(b * MAXDET + s)) * 6;
        o[0] = g_box[b][i][0];
        o[1] = g_box[b][i][1];
        o[2] = g_box[b][i][2];
        o[3] = g_box[b][i][3];
        o[4] = g_sc[b][i];
        o[5] = g_cf[b][i];
    }
}

// ---------------- launch ------------------------------------------------------
extern "C" void kernel_launch(void* const* d_in, const int* in_sizes, int n_in,
                              void* d_out, int out_size)
{
    const float* pred = (const float*)d_in[0];
    int N = in_sizes[0] / (BATCH * 85);
    float* out = (float*)d_out;

    cudaMemsetAsync(out, 0, (size_t)out_size * sizeof(float));
    dim3 g1((N + 255) / 256, BATCH);
    k_score <<<g1, 256>>>(pred, N);
    k_select<<<BATCH, 1024>>>(pred, N);
    k_mask  <<<BATCH * 4, 256>>>();
    k_scan  <<<BATCH, 32>>>(out);
}

// round 3
// speedup vs baseline: 1.8360x; 1.8360x over previous
#include <cuda_runtime.h>
#include <stdint.h>

#define BATCH  8
#define NANCH  100800
#define KPRE   1024
#define MAXDET 100

// ---------------- scratch (static device memory; no runtime allocation) ------
__device__ unsigned int  g_ukey[BATCH][NANCH];
__device__ unsigned char g_cls [BATCH][NANCH];
__device__ unsigned int  g_hist[BATCH][2048];      // pass-A histogram (self-zeroing)
__device__ float         g_box [BATCH][KPRE][4];   // raw xyxy (output boxes)
__device__ float         g_boff[BATCH][KPRE][4];   // class-offset boxes (IoU)
__device__ float         g_area[BATCH][KPRE];
__device__ float         g_sc  [BATCH][KPRE];      // masked score (sorted desc)
__device__ float         g_cf  [BATCH][KPRE];      // class as float
__device__ unsigned int  g_mask[BATCH][KPRE][32];  // suppression bits (j < i)

// ---------------- kernel 1: coalesced score / argmax / key / histogram -------
__global__ void __launch_bounds__(96) k_score(const float* __restrict__ pred)
{
    __shared__ float    tile[3][2720];     // 3 warps x 32 anchors x 85 floats
    __shared__ unsigned shist[2048];

    int b = blockIdx.y;
    int w = threadIdx.x >> 5, l = threadIdx.x & 31;
    for (int i = threadIdx.x; i < 2048; i += 96) shist[i] = 0;

    int base = blockIdx.x * 96 + w * 32;                 // 1050*96 == 100800 exactly
    const float4* p4 = (const float4*)(pred + ((size_t)b * NANCH + base) * 85);
    float4* t4 = (float4*)tile[w];
#pragma unroll
    for (int k = 0; k < 21; ++k) t4[k * 32 + l] = p4[k * 32 + l];
    if (l < 8) t4[672 + l] = p4[672 + l];                // 680 float4 = 2720 floats
    __syncthreads();

    const float* row = &tile[w][l * 85];                 // stride 85: conflict-free
    float obj  = row[4];
    float best = __fmul_rn(row[5], obj);
    int   bi   = 0;
#pragma unroll
    for (int c = 1; c < 80; ++c) {
        float v = __fmul_rn(row[5 + c], obj);
        if (v > best) { best = v; bi = c; }              // strict > == first argmax
    }
    bool  valid = (obj > 0.25f) && (best > 0.25f);
    float sm    = valid ? best : -1.0f;
    int   sb    = __float_as_int(sm);
    unsigned u  = (unsigned)sb ^ ((sb < 0) ? 0xFFFFFFFFu : 0x80000000u);
    int n = base + l;
    g_ukey[b][n] = u;
    g_cls [b][n] = (unsigned char)bi;

    // warp-aggregated smem histogram of top 11 key bits
    unsigned bin   = u >> 21;
    unsigned peers = __match_any_sync(0xFFFFFFFFu, bin);
    if ((int)l == __ffs(peers) - 1) atomicAdd(&shist[bin], (unsigned)__popc(peers));
    __syncthreads();
    for (int i = threadIdx.x; i < 2048; i += 96) {
        unsigned v = shist[i];
        if (v) atomicAdd(&g_hist[b][i], v);
    }
}

// ---------------- kernel 2: exact top-1024 (radix select) + sort + gather ----
__device__ __forceinline__ void hist_add(unsigned* hist, unsigned bin, bool q)
{
    unsigned qm = __ballot_sync(0xFFFFFFFFu, q);
    if (q) {
        unsigned peers = __match_any_sync(qm, bin);
        int ld = __ffs(peers) - 1;
        if ((int)(threadIdx.x & 31) == ld) atomicAdd(&hist[bin], (unsigned)__popc(peers));
    }
}

__device__ __forceinline__ void find_bin(unsigned* hist, unsigned* chunkSum,
                                         int NB, unsigned K, unsigned* sres, int tid)
{
    int nch = NB >> 5;
    if (tid < nch) {
        unsigned s = 0;
        int base = tid << 5;
#pragma unroll 8
        for (int i = 0; i < 32; ++i) s += hist[base + i];
        chunkSum[tid] = s;
    }
    __syncthreads();
    if (tid == 0) {
        unsigned acc = 0;
        int c = nch - 1;
        for (;; --c) {
            unsigned cs = chunkSum[c];
            if (acc + cs >= K) break;
            acc += cs;
        }
        int bin = (c << 5) + 31;
        for (;; --bin) {
            unsigned hv = hist[bin];
            if (acc + hv >= K) break;
            acc += hv;
        }
        sres[0] = (unsigned)bin;
        sres[1] = acc;           // count strictly above bin
    }
    __syncthreads();
}

#define N4      (NANCH / 4)                   // 25200
#define N4ITERS ((N4 + 1023) / 1024)          // 25 (uniform across ALL threads)

__global__ void __launch_bounds__(1024) k_select(const float* __restrict__ pred)
{
    __shared__ unsigned hist[2048];
    __shared__ unsigned chunkSum[64];
    __shared__ unsigned sres[2];
    __shared__ unsigned long long selKey[KPRE];
    __shared__ int eqIdx[2048];
    __shared__ int s_cntGt, s_cntEq;

    int b = blockIdx.x, tid = threadIdx.x;
    const uint4* uk4 = (const uint4*)&g_ukey[b][0];

    // ---- pass A: precomputed histogram (load + self-zero for next replay) ----
    hist[tid] = g_hist[b][tid];
    hist[tid + 1024] = g_hist[b][tid + 1024];
    __syncthreads();
    g_hist[b][tid] = 0; g_hist[b][tid + 1024] = 0;
    find_bin(hist, chunkSum, 2048, KPRE, sres, tid);
    unsigned b1 = sres[0], gt1 = sres[1], K1 = KPRE - gt1;
    __syncthreads();

    // ---- pass B: mid 11 bits (uniform iteration count: warp-sync safe) ----
    hist[tid] = 0; hist[tid + 1024] = 0;
    __syncthreads();
    for (int it = 0; it < N4ITERS; ++it) {
        int t = it * 1024 + tid;
        bool act = t < N4;
        uint4 q = act ? uk4[t] : make_uint4(0u, 0u, 0u, 0u);
        hist_add(hist, (q.x >> 10) & 2047u, act && ((q.x >> 21) == b1));
        hist_add(hist, (q.y >> 10) & 2047u, act && ((q.y >> 21) == b1));
        hist_add(hist, (q.z >> 10) & 2047u, act && ((q.z >> 21) == b1));
        hist_add(hist, (q.w >> 10) & 2047u, act && ((q.w >> 21) == b1));
    }
    __syncthreads();
    find_bin(hist, chunkSum, 2048, K1, sres, tid);
    unsigned b2 = sres[0], gt2 = sres[1], K2 = K1 - gt2;
    unsigned pref = (b1 << 11) | b2;
    __syncthreads();

    // ---- pass C: low 10 bits ----
    hist[tid] = 0;
    __syncthreads();
    for (int it = 0; it < N4ITERS; ++it) {
        int t = it * 1024 + tid;
        bool act = t < N4;
        uint4 q = act ? uk4[t] : make_uint4(0u, 0u, 0u, 0u);
        hist_add(hist, q.x & 1023u, act && ((q.x >> 10) == pref));
        hist_add(hist, q.y & 1023u, act && ((q.y >> 10) == pref));
        hist_add(hist, q.z & 1023u, act && ((q.z >> 10) == pref));
        hist_add(hist, q.w & 1023u, act && ((q.w >> 10) == pref));
    }
    __syncthreads();
    find_bin(hist, chunkSum, 1024, K2, sres, tid);
    unsigned b3 = sres[0], gt3 = sres[1], K3 = K2 - gt3;  // # elems == pivot to take
    unsigned ustar = (b1 << 21) | (b2 << 10) | b3;
    int totalGt = (int)(KPRE - K3);

    if (tid == 0) { s_cntGt = 0; s_cntEq = 0; }
    __syncthreads();

    // ---- pass D: compact (atomics only; no warp-sync intrinsics) ----
    for (int it = 0; it < N4ITERS; ++it) {
        int t = it * 1024 + tid;
        if (t >= N4) break;
        uint4 q = uk4[t];
        unsigned uu[4] = {q.x, q.y, q.z, q.w};
#pragma unroll
        for (int j = 0; j < 4; ++j) {
            unsigned u = uu[j];
            int n = 4 * t + j;
            if (u > ustar) {
                int p = atomicAdd(&s_cntGt, 1);
                selKey[p] = ((unsigned long long)u << 32) | (unsigned)(~n);
            } else if (u == ustar) {
                int qq = atomicAdd(&s_cntEq, 1);
                if (qq < 2048) eqIdx[qq] = n;
            }
        }
    }
    __syncthreads();

    // ---- pass E: tie resolution by smallest index (jax top_k semantics) ----
    int E = s_cntEq; if (E > 2048) E = 2048;
    for (int t = tid; t < E; t += 1024) {
        int my = eqIdx[t], r = 0;
        for (int s = 0; s < E; ++s) r += (eqIdx[s] < my);
        if (r < (int)K3)
            selKey[totalGt + r] = ((unsigned long long)ustar << 32) | (unsigned)(~my);
    }
    __syncthreads();

    // ---- bitonic sort descending (ties -> smaller index first via ~n) ----
    for (int k = 2; k <= KPRE; k <<= 1) {
        for (int j = k >> 1; j > 0; j >>= 1) {
            int ixj = tid ^ j;
            if (ixj > tid) {
                unsigned long long a = selKey[tid], c2 = selKey[ixj];
                bool desc = ((tid & k) == 0);
                if (desc ? (a < c2) : (a > c2)) { selKey[tid] = c2; selKey[ixj] = a; }
            }
            __syncthreads();
        }
    }

    // ---- gather boxes / class / score (bit-exact reference arithmetic) ----
    {
        unsigned long long key = selKey[tid];
        unsigned n = ~((unsigned)(key & 0xFFFFFFFFull));
        unsigned u = (unsigned)(key >> 32);
        unsigned sb = (u & 0x80000000u) ? (u ^ 0x80000000u) : ~u;
        float sc = __int_as_float((int)sb);
        const float* p = pred + ((size_t)b * NANCH + n) * 85;
        float cx = __ldg(p), cy = __ldg(p + 1), w = __ldg(p + 2), h = __ldg(p + 3);
        float hw = __fmul_rn(w, 0.5f), hh = __fmul_rn(h, 0.5f);
        float x1 = __fsub_rn(cx, hw), y1 = __fsub_rn(cy, hh);
        float x2 = __fadd_rn(cx, hw), y2 = __fadd_rn(cy, hh);
        float cf = (float)(int)g_cls[b][n];
        float off = __fmul_rn(cf, 7680.0f);
        float o0 = __fadd_rn(x1, off), o1 = __fadd_rn(y1, off);
        float o2 = __fadd_rn(x2, off), o3 = __fadd_rn(y2, off);
        g_box [b][tid][0] = x1; g_box [b][tid][1] = y1;
        g_box [b][tid][2] = x2; g_box [b][tid][3] = y2;
        g_boff[b][tid][0] = o0; g_boff[b][tid][1] = o1;
        g_boff[b][tid][2] = o2; g_boff[b][tid][3] = o3;
        g_area[b][tid] = __fmul_rn(__fsub_rn(o2, o0), __fsub_rn(o3, o1));
        g_sc  [b][tid] = sc;
        g_cf  [b][tid] = cf;
    }
}

// ---------------- kernel 3a: suppression bitmask matrix (row,word parallel) ---
__global__ void __launch_bounds__(256) k_mask()
{
    __shared__ float s0[KPRE], s1[KPRE], s2[KPRE], s3[KPRE], sar[KPRE];
    int b  = blockIdx.y;
    int rc = blockIdx.x;                       // rows [8rc, 8rc+8)
    int i  = (rc << 3) + (threadIdx.x >> 5);   // one warp per row
    int w  = threadIdx.x & 31;                 // one lane per 32-bit word

    int nload = (rc << 3) + 8;                 // need boxes j < 8rc+8
    for (int t = threadIdx.x; t < nload; t += 256) {
        float4 f = ((const float4*)g_boff[b])[t];
        s0[t] = f.x; s1[t] = f.y; s2[t] = f.z; s3[t] = f.w;
        sar[t] = g_area[b][t];
    }
    __syncthreads();

    unsigned m = 0;
    if (w <= (i >> 5)) {
        float a0 = s0[i], a1 = s1[i], a2 = s2[i], a3 = s3[i], aa = sar[i];
        int base = w << 5;
        int lim = i - base; if (lim > 32) lim = 32;
        for (int jj = 0; jj < lim; ++jj) {
            int j = base + jj;
            float xx1 = fmaxf(a0, s0[j]);
            float yy1 = fmaxf(a1, s1[j]);
            float xx2 = fminf(a2, s2[j]);
            float yy2 = fminf(a3, s3[j]);
            float ww = fmaxf(__fsub_rn(xx2, xx1), 0.0f);
            float hh = fmaxf(__fsub_rn(yy2, yy1), 0.0f);
            float inter = __fmul_rn(ww, hh);
            float uni = __fsub_rn(__fadd_rn(aa, sar[j]), inter);
            float iou = __fdiv_rn(inter, __fadd_rn(uni, 1e-7f));
            if (iou > 0.45f) m |= (1u << jj);
        }
    }
    g_mask[b][i][w] = m;
}

// ---------------- kernel 3b: serial greedy scan (1 warp / batch) --------------
__global__ void __launch_bounds__(32) k_scan(float* __restrict__ out)
{
    __shared__ int list[MAXDET];
    int b = blockIdx.x;
    int l = threadIdx.x;

    // valid count V (scores sorted desc, so valid == prefix); coalesced loads
    int cnt = 0;
#pragma unroll
    for (int j = 0; j < 32; ++j) cnt += (g_sc[b][(j << 5) + l] > 0.0f) ? 1 : 0;
    for (int o = 16; o; o >>= 1) cnt += __shfl_xor_sync(0xFFFFFFFFu, cnt, o);
    int V = cnt;

    unsigned kept = 0;                 // lane l owns keep-bits for rows [32l,32l+32)
    int kc = 0;
    const unsigned* mrow = &g_mask[b][0][0];
    unsigned mA[8], mB[8];
#pragma unroll
    for (int k = 0; k < 8; ++k) mA[k] = mrow[(k << 5) + l];

    for (int base = 0; base < KPRE; base += 8) {
#pragma unroll
        for (int k = 0; k < 8; ++k) {
            int r = base + 8 + k;
            mB[k] = (r < KPRE) ? mrow[(r << 5) + l] : 0u;
        }
        // 8-bit "suppressed by existing kept" mask for this group
        unsigned hit8 = 0;
#pragma unroll
        for (int k = 0; k < 8; ++k) hit8 |= ((mA[k] & kept) ? 1u : 0u) << k;
        unsigned grpHit = __reduce_or_sync(0xFFFFFFFFu, hit8);

        int wg = base >> 5;            // all 8 rows live in word wg (8 | 32)
        int add = 0;
        if (l == wg) {
            unsigned newBits = 0;
            int kcl = kc;
#pragma unroll
            for (int k = 0; k < 8; ++k) {
                int i = base + k;
                bool sup = ((grpHit >> k) & 1u) != 0u || (mA[k] & newBits) != 0u;
                if (i < V && !sup) {
                    newBits |= 1u << (i & 31);
                    if (kcl < MAXDET) list[kcl] = i;
                    kcl++; add++;
                }
            }
            kept |= newBits;
        }
        kc += __shfl_sync(0xFFFFFFFFu, add, wg);
        if (kc >= MAXDET) break;       // only first 100 kept are observable
#pragma unroll
        for (int k = 0; k < 8; ++k) mA[k] = mB[k];
    }
    __syncwarp();

    int K = kc < MAXDET ? kc : MAXDET;
    for (int s = l; s < K; s += 32) {
        int i = list[s];
        float* o = out + ((size_t)(b * MAXDET + s)) * 6;
        o[0] = g_box[b][i][0];
        o[1] = g_box[b][i][1];
        o[2] = g_box[b][i][2];
        o[3] = g_box[b][i][3];
        o[4] = g_sc[b][i];
        o[5] = g_cf[b][i];
    }
}

// ---------------- launch ------------------------------------------------------
extern "C" void kernel_launch(void* const* d_in, const int* in_sizes, int n_in,
                              void* d_out, int out_size)
{
    const float* pred = (const float*)d_in[0];
    float* out = (float*)d_out;

    cudaMemsetAsync(out, 0, (size_t)out_size * sizeof(float));
    k_score <<<dim3(1050, BATCH), 96>>>(pred);
    k_select<<<BATCH, 1024>>>(pred);
    k_mask  <<<dim3(128, BATCH), 256>>>();
    k_scan  <<<BATCH, 32>>>(out);
}

// round 4
// speedup vs baseline: 1.9498x; 1.0620x over previous
#include <cuda_runtime.h>
#include <stdint.h>

#define BATCH  8
#define NANCH  100800
#define KPRE   1024
#define MAXDET 100

// ---------------- scratch (static device memory; no runtime allocation) ------
__device__ unsigned int  g_ukey[BATCH][NANCH];
__device__ unsigned char g_cls [BATCH][NANCH];
__device__ unsigned int  g_hist[BATCH][2048];      // pass-A histogram (self-zeroing)
__device__ float         g_box [BATCH][KPRE][4];   // raw xyxy (output boxes)
__device__ float         g_boff[BATCH][KPRE][4];   // class-offset boxes (IoU)
__device__ float         g_area[BATCH][KPRE];
__device__ float         g_sc  [BATCH][KPRE];      // masked score (sorted desc)
__device__ float         g_cf  [BATCH][KPRE];      // class as float
__device__ unsigned int  g_mask[BATCH][KPRE][32];  // suppression bits (j < i)

// ---------------- kernel 1: coalesced score / argmax / key / histogram -------
__global__ void __launch_bounds__(96) k_score(const float* __restrict__ pred)
{
    __shared__ float    tile[3][2720];     // 3 warps x 32 anchors x 85 floats
    __shared__ unsigned shist[2048];

    int b = blockIdx.y;
    int w = threadIdx.x >> 5, l = threadIdx.x & 31;
    for (int i = threadIdx.x; i < 2048; i += 96) shist[i] = 0;

    int base = blockIdx.x * 96 + w * 32;                 // 1050*96 == 100800 exactly
    const float4* p4 = (const float4*)(pred + ((size_t)b * NANCH + base) * 85);
    float4* t4 = (float4*)tile[w];
#pragma unroll
    for (int k = 0; k < 21; ++k) t4[k * 32 + l] = p4[k * 32 + l];
    if (l < 8) t4[672 + l] = p4[672 + l];                // 680 float4 = 2720 floats
    __syncthreads();

    const float* row = &tile[w][l * 85];                 // stride 85: conflict-free
    float obj  = row[4];
    float best = __fmul_rn(row[5], obj);
    int   bi   = 0;
#pragma unroll
    for (int c = 1; c < 80; ++c) {
        float v = __fmul_rn(row[5 + c], obj);
        if (v > best) { best = v; bi = c; }              // strict > == first argmax
    }
    bool  valid = (obj > 0.25f) && (best > 0.25f);
    float sm    = valid ? best : -1.0f;
    int   sb    = __float_as_int(sm);
    unsigned u  = (unsigned)sb ^ ((sb < 0) ? 0xFFFFFFFFu : 0x80000000u);
    int n = base + l;
    g_ukey[b][n] = u;
    g_cls [b][n] = (unsigned char)bi;

    // warp-aggregated smem histogram of top 11 key bits
    unsigned bin   = u >> 21;
    unsigned peers = __match_any_sync(0xFFFFFFFFu, bin);
    if ((int)l == __ffs(peers) - 1) atomicAdd(&shist[bin], (unsigned)__popc(peers));
    __syncthreads();
    for (int i = threadIdx.x; i < 2048; i += 96) {
        unsigned v = shist[i];
        if (v) atomicAdd(&g_hist[b][i], v);
    }
}

// ---------------- kernel 2: exact top-1024 (radix select) + sort + gather ----
__device__ __forceinline__ void hist_add(unsigned* hist, unsigned bin, bool q)
{
    unsigned qm = __ballot_sync(0xFFFFFFFFu, q);
    if (q) {
        unsigned peers = __match_any_sync(qm, bin);
        int ld = __ffs(peers) - 1;
        if ((int)(threadIdx.x & 31) == ld) atomicAdd(&hist[bin], (unsigned)__popc(peers));
    }
}

__device__ __forceinline__ void find_bin(unsigned* hist, unsigned* chunkSum,
                                         int NB, unsigned K, unsigned* sres, int tid)
{
    int nch = NB >> 5;
    if (tid < nch) {
        unsigned s = 0;
        int base = tid << 5;
#pragma unroll 8
        for (int i = 0; i < 32; ++i) s += hist[base + i];
        chunkSum[tid] = s;
    }
    __syncthreads();
    if (tid == 0) {
        unsigned acc = 0;
        int c = nch - 1;
        for (;; --c) {
            unsigned cs = chunkSum[c];
            if (acc + cs >= K) break;
            acc += cs;
        }
        int bin = (c << 5) + 31;
        for (;; --bin) {
            unsigned hv = hist[bin];
            if (acc + hv >= K) break;
            acc += hv;
        }
        sres[0] = (unsigned)bin;
        sres[1] = acc;           // count strictly above bin
    }
    __syncthreads();
}

#define N4      (NANCH / 4)                   // 25200
#define NBATCH4 7                             // 7 * 4 * 1024 = 28672 >= 25200

__device__ __forceinline__ unsigned long long umaxll(unsigned long long a, unsigned long long b)
{ return a > b ? a : b; }
__device__ __forceinline__ unsigned long long uminll(unsigned long long a, unsigned long long b)
{ return a < b ? a : b; }

__global__ void __launch_bounds__(1024) k_select(const float* __restrict__ pred)
{
    __shared__ unsigned hist[2048];
    __shared__ unsigned chunkSum[64];
    __shared__ unsigned sres[2];
    __shared__ unsigned long long selKey[KPRE];   // also sort buffer 0
    __shared__ unsigned long long sbuf1[KPRE];    // eqIdx storage + sort buffer 1
    __shared__ int s_cntGt, s_cntEq;

    int b = blockIdx.x, tid = threadIdx.x;
    const uint4* uk4 = (const uint4*)&g_ukey[b][0];
    int* eqIdx = (int*)sbuf1;                     // 2048 ints

    // ---- pass A: precomputed histogram (load + self-zero for next replay) ----
    hist[tid] = g_hist[b][tid];
    hist[tid + 1024] = g_hist[b][tid + 1024];
    __syncthreads();
    g_hist[b][tid] = 0; g_hist[b][tid + 1024] = 0;
    find_bin(hist, chunkSum, 2048, KPRE, sres, tid);
    unsigned b1 = sres[0], gt1 = sres[1], K1 = KPRE - gt1;
    __syncthreads();

    // ---- pass B: mid 11 bits (uniform iterations, MLP=4) ----
    hist[tid] = 0; hist[tid + 1024] = 0;
    __syncthreads();
    for (int it = 0; it < NBATCH4; ++it) {
        uint4 q[4]; bool a[4];
#pragma unroll
        for (int s = 0; s < 4; ++s) {
            int t = it * 4096 + s * 1024 + tid;
            a[s] = t < N4;
            q[s] = a[s] ? uk4[t] : make_uint4(0u, 0u, 0u, 0u);
        }
#pragma unroll
        for (int s = 0; s < 4; ++s) {
            hist_add(hist, (q[s].x >> 10) & 2047u, a[s] && ((q[s].x >> 21) == b1));
            hist_add(hist, (q[s].y >> 10) & 2047u, a[s] && ((q[s].y >> 21) == b1));
            hist_add(hist, (q[s].z >> 10) & 2047u, a[s] && ((q[s].z >> 21) == b1));
            hist_add(hist, (q[s].w >> 10) & 2047u, a[s] && ((q[s].w >> 21) == b1));
        }
    }
    __syncthreads();
    find_bin(hist, chunkSum, 2048, K1, sres, tid);
    unsigned b2 = sres[0], gt2 = sres[1], K2 = K1 - gt2;
    unsigned pref = (b1 << 11) | b2;
    __syncthreads();

    // ---- pass C: low 10 bits ----
    hist[tid] = 0;
    __syncthreads();
    for (int it = 0; it < NBATCH4; ++it) {
        uint4 q[4]; bool a[4];
#pragma unroll
        for (int s = 0; s < 4; ++s) {
            int t = it * 4096 + s * 1024 + tid;
            a[s] = t < N4;
            q[s] = a[s] ? uk4[t] : make_uint4(0u, 0u, 0u, 0u);
        }
#pragma unroll
        for (int s = 0; s < 4; ++s) {
            hist_add(hist, q[s].x & 1023u, a[s] && ((q[s].x >> 10) == pref));
            hist_add(hist, q[s].y & 1023u, a[s] && ((q[s].y >> 10) == pref));
            hist_add(hist, q[s].z & 1023u, a[s] && ((q[s].z >> 10) == pref));
            hist_add(hist, q[s].w & 1023u, a[s] && ((q[s].w >> 10) == pref));
        }
    }
    __syncthreads();
    find_bin(hist, chunkSum, 1024, K2, sres, tid);
    unsigned b3 = sres[0], gt3 = sres[1], K3 = K2 - gt3;  // # elems == pivot to take
    unsigned ustar = (b1 << 21) | (b2 << 10) | b3;
    int totalGt = (int)(KPRE - K3);                        // count strictly > pivot

    if (tid == 0) { s_cntGt = 0; s_cntEq = 0; }
    __syncthreads();

    // ---- pass D: compact (MLP=4 batched) ----
    for (int it = 0; it < NBATCH4; ++it) {
        uint4 q[4]; bool a[4];
#pragma unroll
        for (int s = 0; s < 4; ++s) {
            int t = it * 4096 + s * 1024 + tid;
            a[s] = t < N4;
            q[s] = a[s] ? uk4[t] : make_uint4(0u, 0u, 0u, 0u);
        }
#pragma unroll
        for (int s = 0; s < 4; ++s) {
            if (!a[s]) continue;
            int t = it * 4096 + s * 1024 + tid;
            unsigned uu[4] = {q[s].x, q[s].y, q[s].z, q[s].w};
#pragma unroll
            for (int j = 0; j < 4; ++j) {
                unsigned u = uu[j];
                int n = 4 * t + j;
                if (u > ustar) {
                    int p = atomicAdd(&s_cntGt, 1);
                    selKey[p] = ((unsigned long long)u << 32) | (unsigned)(~n);
                } else if (u == ustar) {
                    int qq = atomicAdd(&s_cntEq, 1);
                    if (qq < 2048) eqIdx[qq] = n;
                }
            }
        }
    }
    __syncthreads();

    // ---- pass E: tie resolution by smallest index (jax top_k semantics) ----
    int E = s_cntEq; if (E > 2048) E = 2048;
    for (int t = tid; t < E; t += 1024) {
        int my = eqIdx[t], r = 0;
        for (int s = 0; s < E; ++s) r += (eqIdx[s] < my);
        if (r < (int)K3)
            selKey[totalGt + r] = ((unsigned long long)ustar << 32) | (unsigned)(~my);
    }
    __syncthreads();

    // ---- hybrid bitonic sort, descending (smem stages j>=32, shfl j<=16) ----
    unsigned long long key = selKey[tid];
    int cur = 0;                                           // next smem buffer
    // k = 2..32: fully intra-warp
#pragma unroll
    for (int k = 2; k <= 32; k <<= 1) {
        bool desc = ((tid & k) == 0);
#pragma unroll
        for (int j = k >> 1; j > 0; j >>= 1) {
            unsigned long long other = __shfl_xor_sync(0xFFFFFFFFu, key, j);
            bool lower = (tid & j) == 0;
            key = (lower == desc) ? umaxll(key, other) : uminll(key, other);
        }
    }
    __syncthreads();                                       // selKey reads done; reuse as buffer
    for (int k = 64; k <= KPRE; k <<= 1) {
        bool desc = ((tid & k) == 0);
        for (int j = k >> 1; j >= 32; j >>= 1) {
            unsigned long long* B = cur ? sbuf1 : selKey;
            B[tid] = key;
            __syncthreads();
            unsigned long long other = B[tid ^ j];
            bool lower = (tid & j) == 0;
            key = (lower == desc) ? umaxll(key, other) : uminll(key, other);
            cur ^= 1;
        }
#pragma unroll
        for (int j = 16; j > 0; j >>= 1) {
            unsigned long long other = __shfl_xor_sync(0xFFFFFFFFu, key, j);
            bool lower = (tid & j) == 0;
            key = (lower == desc) ? umaxll(key, other) : uminll(key, other);
        }
    }

    // ---- gather boxes / class / score (bit-exact reference arithmetic) ----
    {
        unsigned n = ~((unsigned)(key & 0xFFFFFFFFull));
        unsigned u = (unsigned)(key >> 32);
        unsigned sb = (u & 0x80000000u) ? (u ^ 0x80000000u) : ~u;
        float sc = __int_as_float((int)sb);
        const float* p = pred + ((size_t)b * NANCH + n) * 85;
        float cx = __ldg(p), cy = __ldg(p + 1), w = __ldg(p + 2), h = __ldg(p + 3);
        float hw = __fmul_rn(w, 0.5f), hh = __fmul_rn(h, 0.5f);
        float x1 = __fsub_rn(cx, hw), y1 = __fsub_rn(cy, hh);
        float x2 = __fadd_rn(cx, hw), y2 = __fadd_rn(cy, hh);
        float cf = (float)(int)g_cls[b][n];
        float off = __fmul_rn(cf, 7680.0f);
        float o0 = __fadd_rn(x1, off), o1 = __fadd_rn(y1, off);
        float o2 = __fadd_rn(x2, off), o3 = __fadd_rn(y2, off);
        g_box [b][tid][0] = x1; g_box [b][tid][1] = y1;
        g_box [b][tid][2] = x2; g_box [b][tid][3] = y2;
        g_boff[b][tid][0] = o0; g_boff[b][tid][1] = o1;
        g_boff[b][tid][2] = o2; g_boff[b][tid][3] = o3;
        g_area[b][tid] = __fmul_rn(__fsub_rn(o2, o0), __fsub_rn(o3, o1));
        g_sc  [b][tid] = sc;
        g_cf  [b][tid] = cf;
    }
}

// ---------------- kernel 3a: suppression bitmask matrix (row,word parallel) ---
__global__ void __launch_bounds__(256) k_mask()
{
    __shared__ float s0[KPRE], s1[KPRE], s2[KPRE], s3[KPRE], sar[KPRE];
    int b  = blockIdx.y;
    int rc = blockIdx.x;                       // rows [8rc, 8rc+8)
    int i  = (rc << 3) + (threadIdx.x >> 5);   // one warp per row
    int w  = threadIdx.x & 31;                 // one lane per 32-bit word

    int nload = (rc << 3) + 8;                 // need boxes j < 8rc+8
    for (int t = threadIdx.x; t < nload; t += 256) {
        float4 f = ((const float4*)g_boff[b])[t];
        s0[t] = f.x; s1[t] = f.y; s2[t] = f.z; s3[t] = f.w;
        sar[t] = g_area[b][t];
    }
    __syncthreads();

    unsigned m = 0;
    if (w <= (i >> 5)) {
        float a0 = s0[i], a1 = s1[i], a2 = s2[i], a3 = s3[i], aa = sar[i];
        int base = w << 5;
        int lim = i - base; if (lim > 32) lim = 32;
        for (int jj = 0; jj < lim; ++jj) {
            int j = base + jj;
            float xx1 = fmaxf(a0, s0[j]);
            float yy1 = fmaxf(a1, s1[j]);
            float xx2 = fminf(a2, s2[j]);
            float yy2 = fminf(a3, s3[j]);
            float ww = fmaxf(__fsub_rn(xx2, xx1), 0.0f);
            float hh = fmaxf(__fsub_rn(yy2, yy1), 0.0f);
            float inter = __fmul_rn(ww, hh);
            float uni = __fsub_rn(__fadd_rn(aa, sar[j]), inter);
            float iou = __fdiv_rn(inter, __fadd_rn(uni, 1e-7f));
            if (iou > 0.45f) m |= (1u << jj);
        }
    }
    g_mask[b][i][w] = m;
}

// ---------------- kernel 3b: greedy scan, smem-staged (256 thr / batch) -------
#define PRELOAD_ROWS 256

__global__ void __launch_bounds__(256) k_scan(float* __restrict__ out)
{
    __shared__ unsigned smask[PRELOAD_ROWS][32];   // 32KB: first 256 mask rows
    __shared__ int list[MAXDET];
    __shared__ int sV;

    int b = blockIdx.x;
    int tid = threadIdx.x;
    int l = tid & 31;

    if (tid == 0) sV = 0;
    const unsigned* gm = &g_mask[b][0][0];
    for (int t = tid; t < PRELOAD_ROWS * 32; t += 256)
        ((unsigned*)smask)[t] = gm[t];

    // V count: 256 threads x float4
    {
        float4 f = ((const float4*)&g_sc[b][0])[tid];
        int c = (f.x > 0.0f) + (f.y > 0.0f) + (f.z > 0.0f) + (f.w > 0.0f);
        for (int o = 16; o; o >>= 1) c += __shfl_xor_sync(0xFFFFFFFFu, c, o);
        __syncthreads();                   // smask loaded, sV initialized
        if (l == 0) atomicAdd(&sV, c);
    }
    __syncthreads();

    int kc = 0;
    if (tid < 32) {                        // warp 0: serial greedy scan
        int V = sV;
        unsigned kept = 0;                 // lane l owns rows [32l, 32l+32)
        unsigned mA[8], mB[8];
#pragma unroll
        for (int k = 0; k < 8; ++k) mA[k] = smask[k][l];

        for (int base = 0; base < KPRE; base += 8) {
#pragma unroll
            for (int k = 0; k < 8; ++k) {
                int r = base + 8 + k;
                mB[k] = (r >= KPRE) ? 0u
                      : (r < PRELOAD_ROWS ? smask[r][l] : gm[(r << 5) + l]);
            }
            unsigned hit8 = 0;
#pragma unroll
            for (int k = 0; k < 8; ++k) hit8 |= ((mA[k] & kept) ? 1u : 0u) << k;
            unsigned grpHit = __reduce_or_sync(0xFFFFFFFFu, hit8);

            int wg = base >> 5;            // all 8 rows live in word wg (8 | 32)
            int add = 0;
            if (l == wg) {
                unsigned newBits = 0;
                int kcl = kc;
#pragma unroll
                for (int k = 0; k < 8; ++k) {
                    int i = base + k;
                    bool sup = ((grpHit >> k) & 1u) != 0u || (mA[k] & newBits) != 0u;
                    if (i < V && !sup) {
                        newBits |= 1u << (i & 31);
                        if (kcl < MAXDET) list[kcl] = i;
                        kcl++; add++;
                    }
                }
                kept |= newBits;
            }
            kc += __shfl_sync(0xFFFFFFFFu, add, wg);
            if (kc >= MAXDET) break;       // only first 100 kept are observable
#pragma unroll
            for (int k = 0; k < 8; ++k) mA[k] = mB[k];
        }
        __syncwarp();

        // write all MAXDET rows (zeros beyond K) — replaces the memset launch
        int K = kc < MAXDET ? kc : MAXDET;
        for (int s = l; s < MAXDET; s += 32) {
            float v0 = 0.f, v1 = 0.f, v2 = 0.f, v3 = 0.f, v4 = 0.f, v5 = 0.f;
            if (s < K) {
                int i = list[s];
                v0 = g_box[b][i][0]; v1 = g_box[b][i][1];
                v2 = g_box[b][i][2]; v3 = g_box[b][i][3];
                v4 = g_sc[b][i];     v5 = g_cf[b][i];
            }
            float* o = out + ((size_t)(b * MAXDET + s)) * 6;
            o[0] = v0; o[1] = v1; o[2] = v2; o[3] = v3; o[4] = v4; o[5] = v5;
        }
    }
}

// ---------------- launch ------------------------------------------------------
extern "C" void kernel_launch(void* const* d_in, const int* in_sizes, int n_in,
                              void* d_out, int out_size)
{
    const float* pred = (const float*)d_in[0];
    float* out = (float*)d_out;

    k_score <<<dim3(1050, BATCH), 96>>>(pred);
    k_select<<<BATCH, 1024>>>(pred);
    k_mask  <<<dim3(128, BATCH), 256>>>();
    k_scan  <<<BATCH, 32 * 8>>>(out);
}

// round 5
// speedup vs baseline: 1.9529x; 1.0016x over previous
#include <cuda_runtime.h>
#include <stdint.h>

#define BATCH  8
#define NANCH  100800
#define KPRE   1024
#define MAXDET 100

// ---------------- scratch (static device memory; no runtime allocation) ------
__device__ unsigned int        g_ukey[BATCH][NANCH];
__device__ unsigned char       g_cls [BATCH][NANCH];
__device__ unsigned int        g_hist[BATCH][2048];     // pass-A hist (self-zeroing)
__device__ unsigned long long  g_cand[BATCH][NANCH];    // pivot-bin candidates
__device__ float               g_box [BATCH][KPRE][4];  // raw xyxy (output boxes)
__device__ float               g_boff[BATCH][KPRE][4];  // class-offset boxes (IoU)
__device__ float               g_area[BATCH][KPRE];
__device__ float               g_sc  [BATCH][KPRE];     // masked score (sorted desc)
__device__ float               g_cf  [BATCH][KPRE];     // class as float
__device__ unsigned int        g_mask[BATCH][KPRE][32]; // suppression bits (j < i)

// ---------------- kernel 1: coalesced score / argmax / key / histogram -------
__global__ void __launch_bounds__(96) k_score(const float* __restrict__ pred)
{
    __shared__ float tile[3][2720];        // 3 warps x 32 anchors x 85 floats

    int b = blockIdx.y;
    int w = threadIdx.x >> 5, l = threadIdx.x & 31;

    int base = blockIdx.x * 96 + w * 32;                 // 1050*96 == 100800 exactly
    const float4* p4 = (const float4*)(pred + ((size_t)b * NANCH + base) * 85);
    float4* t4 = (float4*)tile[w];
#pragma unroll
    for (int k = 0; k < 21; ++k) t4[k * 32 + l] = p4[k * 32 + l];
    if (l < 8) t4[672 + l] = p4[672 + l];                // 680 float4 = 2720 floats
    __syncwarp();                                        // per-warp tile, warp-local

    const float* row = &tile[w][l * 85];                 // stride 85: conflict-free
    float obj = row[4];

    // 4 independent strict-> chains (each keeps first occurrence within chain),
    // merged by (value, then lower index) == min-index-of-max == reference argmax
    float v0 = __fmul_rn(row[5], obj);     int i0 = 0;
    float v1 = __fmul_rn(row[6], obj);     int i1 = 1;
    float v2 = __fmul_rn(row[7], obj);     int i2 = 2;
    float v3 = __fmul_rn(row[8], obj);     int i3 = 3;
#pragma unroll
    for (int t = 1; t < 20; ++t) {
        int c = 4 * t;
        float a = __fmul_rn(row[5 + c],     obj);
        float bq = __fmul_rn(row[6 + c],    obj);
        float cq = __fmul_rn(row[7 + c],    obj);
        float dq = __fmul_rn(row[8 + c],    obj);
        if (a  > v0) { v0 = a;  i0 = c;     }
        if (bq > v1) { v1 = bq; i1 = c + 1; }
        if (cq > v2) { v2 = cq; i2 = c + 2; }
        if (dq > v3) { v3 = dq; i3 = c + 3; }
    }
    float best = v0; int bi = i0;
    if (v1 > best || (v1 == best && i1 < bi)) { best = v1; bi = i1; }
    if (v2 > best || (v2 == best && i2 < bi)) { best = v2; bi = i2; }
    if (v3 > best || (v3 == best && i3 < bi)) { best = v3; bi = i3; }

    bool  valid = (obj > 0.25f) && (best > 0.25f);
    float sm    = valid ? best : -1.0f;
    int   sb    = __float_as_int(sm);
    unsigned u  = (unsigned)sb ^ ((sb < 0) ? 0xFFFFFFFFu : 0x80000000u);
    int n = base + l;
    g_ukey[b][n] = u;
    g_cls [b][n] = (unsigned char)bi;

    // warp-aggregated GLOBAL histogram of top 11 key bits
    unsigned bin   = u >> 21;
    unsigned peers = __match_any_sync(0xFFFFFFFFu, bin);
    if ((int)l == __ffs(peers) - 1) atomicAdd(&g_hist[b][bin], (unsigned)__popc(peers));
}

// ---------------- kernel 2: exact top-1024 (radix select) + sort + gather ----
__device__ __forceinline__ void hist_add(unsigned* hist, unsigned bin, bool q)
{
    unsigned qm = __ballot_sync(0xFFFFFFFFu, q);
    if (q) {
        unsigned peers = __match_any_sync(qm, bin);
        int ld = __ffs(peers) - 1;
        if ((int)(threadIdx.x & 31) == ld) atomicAdd(&hist[bin], (unsigned)__popc(peers));
    }
}

__device__ __forceinline__ void find_bin(unsigned* hist, unsigned* chunkSum,
                                         int NB, unsigned K, unsigned* sres, int tid)
{
    int nch = NB >> 5;
    if (tid < nch) {
        unsigned s = 0;
        int base = tid << 5;
#pragma unroll 8
        for (int i = 0; i < 32; ++i) s += hist[base + i];
        chunkSum[tid] = s;
    }
    __syncthreads();
    if (tid == 0) {
        unsigned acc = 0;
        int c = nch - 1;
        for (;; --c) {
            unsigned cs = chunkSum[c];
            if (acc + cs >= K) break;
            acc += cs;
        }
        int bin = (c << 5) + 31;
        for (;; --bin) {
            unsigned hv = hist[bin];
            if (acc + hv >= K) break;
            acc += hv;
        }
        sres[0] = (unsigned)bin;
        sres[1] = acc;           // count strictly above bin
    }
    __syncthreads();
}

#define N4 (NANCH / 4)                     // 25200

__device__ __forceinline__ unsigned long long umaxll(unsigned long long a, unsigned long long b)
{ return a > b ? a : b; }
__device__ __forceinline__ unsigned long long uminll(unsigned long long a, unsigned long long b)
{ return a < b ? a : b; }

__global__ void __launch_bounds__(1024) k_select(const float* __restrict__ pred)
{
    __shared__ unsigned hist[2048];
    __shared__ unsigned chunkSum[64];
    __shared__ unsigned sres[2];
    __shared__ unsigned long long selKey[KPRE];   // also sort buffer 0
    __shared__ unsigned long long sbuf1[KPRE];    // eqIdx storage + sort buffer 1
    __shared__ int s_cntGt, s_cntEq, s_cntCand;

    int b = blockIdx.x, tid = threadIdx.x;
    const uint4* uk4 = (const uint4*)&g_ukey[b][0];
    unsigned long long* cand = &g_cand[b][0];
    int* eqIdx = (int*)sbuf1;                     // 2048 ints

    // ---- pass A: precomputed histogram (load + self-zero for next replay) ----
    hist[tid] = g_hist[b][tid];
    hist[tid + 1024] = g_hist[b][tid + 1024];
    __syncthreads();
    g_hist[b][tid] = 0; g_hist[b][tid + 1024] = 0;
    find_bin(hist, chunkSum, 2048, KPRE, sres, tid);
    unsigned b1 = sres[0], gt1 = sres[1], K1 = KPRE - gt1;
    int C = (int)hist[b1];                        // candidate count (exact)
    if (tid == 0) { s_cntGt = 0; s_cntEq = 0; s_cntCand = 0; }
    __syncthreads();

    // ---- THE single global scan: compact sure-winners + pivot-bin members ----
    for (int t = tid; t < N4; t += 1024) {
        uint4 q = uk4[t];
        unsigned uu[4] = {q.x, q.y, q.z, q.w};
#pragma unroll
        for (int j = 0; j < 4; ++j) {
            unsigned u = uu[j];
            unsigned hb = u >> 21;
            if (hb >= b1) {
                int n = 4 * t + j;
                unsigned long long key = ((unsigned long long)u << 32) | (unsigned)(~n);
                if (hb > b1) {
                    int p = atomicAdd(&s_cntGt, 1);
                    selKey[p] = key;
                } else {
                    int p = atomicAdd(&s_cntCand, 1);
                    cand[p] = key;
                }
            }
        }
    }
    __syncthreads();

    // ---- pass B: mid 11 bits over candidates only ----
    hist[tid] = 0; hist[tid + 1024] = 0;
    __syncthreads();
    int iters = (C + 1023) >> 10;                 // uniform across ALL threads
    for (int it = 0; it < iters; ++it) {
        int t = (it << 10) + tid;
        bool act = t < C;
        unsigned long long k = act ? cand[t] : 0ull;
        unsigned u = (unsigned)(k >> 32);
        hist_add(hist, (u >> 10) & 2047u, act);
    }
    __syncthreads();
    find_bin(hist, chunkSum, 2048, K1, sres, tid);
    unsigned b2 = sres[0], gt2 = sres[1], K2 = K1 - gt2;
    __syncthreads();

    // ---- pass C: low 10 bits over candidates matching b2 ----
    hist[tid] = 0;
    __syncthreads();
    for (int it = 0; it < iters; ++it) {
        int t = (it << 10) + tid;
        bool act = t < C;
        unsigned long long k = act ? cand[t] : 0ull;
        unsigned u = (unsigned)(k >> 32);
        hist_add(hist, u & 1023u, act && (((u >> 10) & 2047u) == b2));
    }
    __syncthreads();
    find_bin(hist, chunkSum, 1024, K2, sres, tid);
    unsigned b3 = sres[0], gt3 = sres[1], K3 = K2 - gt3;  // # elems == pivot to take
    unsigned ustar = (b1 << 21) | (b2 << 10) | b3;
    int totalGt = (int)(KPRE - K3);                        // count strictly > pivot
    __syncthreads();

    // ---- pass D: partition candidates (no collectives; divergence-safe) ----
    for (int t = tid; t < C; t += 1024) {
        unsigned long long k = cand[t];
        unsigned u = (unsigned)(k >> 32);
        if (u > ustar) {
            int p = atomicAdd(&s_cntGt, 1);
            selKey[p] = k;
        } else if (u == ustar) {
            int qq = atomicAdd(&s_cntEq, 1);
            if (qq < 2048) eqIdx[qq] = (int)~((unsigned)(k & 0xFFFFFFFFull));
        }
    }
    __syncthreads();

    // ---- pass E: tie resolution by smallest index (jax top_k semantics) ----
    int E = s_cntEq; if (E > 2048) E = 2048;
    for (int t = tid; t < E; t += 1024) {
        int my = eqIdx[t], r = 0;
        for (int s = 0; s < E; ++s) r += (eqIdx[s] < my);
        if (r < (int)K3)
            selKey[totalGt + r] = ((unsigned long long)ustar << 32) | (unsigned)(~my);
    }
    __syncthreads();

    // ---- hybrid bitonic sort, descending (smem stages j>=32, shfl j<=16) ----
    unsigned long long key = selKey[tid];
    int cur = 0;                                           // next smem buffer
#pragma unroll
    for (int k = 2; k <= 32; k <<= 1) {
        bool desc = ((tid & k) == 0);
#pragma unroll
        for (int j = k >> 1; j > 0; j >>= 1) {
            unsigned long long other = __shfl_xor_sync(0xFFFFFFFFu, key, j);
            bool lower = (tid & j) == 0;
            key = (lower == desc) ? umaxll(key, other) : uminll(key, other);
        }
    }
    __syncthreads();                                       // selKey reads done; reuse
    for (int k = 64; k <= KPRE; k <<= 1) {
        bool desc = ((tid & k) == 0);
        for (int j = k >> 1; j >= 32; j >>= 1) {
            unsigned long long* B = cur ? sbuf1 : selKey;
            B[tid] = key;
            __syncthreads();
            unsigned long long other = B[tid ^ j];
            bool lower = (tid & j) == 0;
            key = (lower == desc) ? umaxll(key, other) : uminll(key, other);
            cur ^= 1;
        }
#pragma unroll
        for (int j = 16; j > 0; j >>= 1) {
            unsigned long long other = __shfl_xor_sync(0xFFFFFFFFu, key, j);
            bool lower = (tid & j) == 0;
            key = (lower == desc) ? umaxll(key, other) : uminll(key, other);
        }
    }

    // ---- gather boxes / class / score (bit-exact reference arithmetic) ----
    {
        unsigned n = ~((unsigned)(key & 0xFFFFFFFFull));
        unsigned u = (unsigned)(key >> 32);
        unsigned sb = (u & 0x80000000u) ? (u ^ 0x80000000u) : ~u;
        float sc = __int_as_float((int)sb);
        const float* p = pred + ((size_t)b * NANCH + n) * 85;
        float cx = __ldg(p), cy = __ldg(p + 1), w = __ldg(p + 2), h = __ldg(p + 3);
        float hw = __fmul_rn(w, 0.5f), hh = __fmul_rn(h, 0.5f);
        float x1 = __fsub_rn(cx, hw), y1 = __fsub_rn(cy, hh);
        float x2 = __fadd_rn(cx, hw), y2 = __fadd_rn(cy, hh);
        float cf = (float)(int)g_cls[b][n];
        float off = __fmul_rn(cf, 7680.0f);
        float o0 = __fadd_rn(x1, off), o1 = __fadd_rn(y1, off);
        float o2 = __fadd_rn(x2, off), o3 = __fadd_rn(y2, off);
        g_box [b][tid][0] = x1; g_box [b][tid][1] = y1;
        g_box [b][tid][2] = x2; g_box [b][tid][3] = y2;
        g_boff[b][tid][0] = o0; g_boff[b][tid][1] = o1;
        g_boff[b][tid][2] = o2; g_boff[b][tid][3] = o3;
        g_area[b][tid] = __fmul_rn(__fsub_rn(o2, o0), __fsub_rn(o3, o1));
        g_sc  [b][tid] = sc;
        g_cf  [b][tid] = cf;
    }
}

// ---------------- kernel 3a: suppression bitmask matrix (row,word parallel) ---
__global__ void __launch_bounds__(256) k_mask()
{
    __shared__ float s0[KPRE], s1[KPRE], s2[KPRE], s3[KPRE], sar[KPRE];
    int b  = blockIdx.y;
    int rc = blockIdx.x;                       // rows [8rc, 8rc+8)
    int i  = (rc << 3) + (threadIdx.x >> 5);   // one warp per row
    int w  = threadIdx.x & 31;                 // one lane per 32-bit word

    int nload = (rc << 3) + 8;                 // need boxes j < 8rc+8
    for (int t = threadIdx.x; t < nload; t += 256) {
        float4 f = ((const float4*)g_boff[b])[t];
        s0[t] = f.x; s1[t] = f.y; s2[t] = f.z; s3[t] = f.w;
        sar[t] = g_area[b][t];
    }
    __syncthreads();

    unsigned m = 0;
    if (w <= (i >> 5)) {
        float a0 = s0[i], a1 = s1[i], a2 = s2[i], a3 = s3[i], aa = sar[i];
        int base = w << 5;
        int lim = i - base; if (lim > 32) lim = 32;
        for (int jj = 0; jj < lim; ++jj) {
            int j = base + jj;
            float xx1 = fmaxf(a0, s0[j]);
            float yy1 = fmaxf(a1, s1[j]);
            float xx2 = fminf(a2, s2[j]);
            float yy2 = fminf(a3, s3[j]);
            float ww = fmaxf(__fsub_rn(xx2, xx1), 0.0f);
            float hh = fmaxf(__fsub_rn(yy2, yy1), 0.0f);
            float inter = __fmul_rn(ww, hh);
            float uni = __fsub_rn(__fadd_rn(aa, sar[j]), inter);
            float iou = __fdiv_rn(inter, __fadd_rn(uni, 1e-7f));
            if (iou > 0.45f) m |= (1u << jj);
        }
    }
    g_mask[b][i][w] = m;
}

// ---------------- kernel 3b: greedy scan, 32 rows per collective step ---------
__global__ void __launch_bounds__(256) k_scan(float* __restrict__ out)
{
    __shared__ int list[MAXDET];
    __shared__ int sV;

    int b = blockIdx.x;
    int tid = threadIdx.x;
    int l = tid & 31;

    if (tid == 0) sV = 0;
    __syncthreads();

    // V count: 256 threads x float4 (scores sorted desc -> valid == prefix)
    {
        float4 f = ((const float4*)&g_sc[b][0])[tid];
        int c = (f.x > 0.0f) + (f.y > 0.0f) + (f.z > 0.0f) + (f.w > 0.0f);
        for (int o = 16; o; o >>= 1) c += __shfl_xor_sync(0xFFFFFFFFu, c, o);
        if (l == 0) atomicAdd(&sV, c);
    }
    __syncthreads();

    int kc = 0;
    if (tid < 32) {                            // warp 0: serial greedy scan
        int V = sV;
        unsigned kept = 0;                     // lane l owns rows [32l, 32l+32)
        const unsigned* gm = &g_mask[b][0][0];
        unsigned mA[32], mB[32];
#pragma unroll
        for (int k = 0; k < 32; ++k) mA[k] = gm[(k << 5) + l];

        for (int base = 0; base < KPRE; base += 32) {
            if (base + 32 < KPRE) {
#pragma unroll
                for (int k = 0; k < 32; ++k) mB[k] = gm[((base + 32 + k) << 5) + l];
            }
            unsigned hv = 0;
#pragma unroll
            for (int k = 0; k < 32; ++k) hv |= ((mA[k] & kept) ? 1u : 0u) << k;
            unsigned grpHit = __reduce_or_sync(0xFFFFFFFFu, hv);

            int wg = base >> 5;                // rows of this group live in word wg
            int add = 0;
            if (l == wg) {
                unsigned newBits = 0;
                int kcl = kc;
#pragma unroll
                for (int k = 0; k < 32; ++k) {
                    int i = base + k;
                    bool sup = ((grpHit >> k) & 1u) != 0u || (mA[k] & newBits) != 0u;
                    if (i < V && !sup) {
                        newBits |= 1u << k;    // i & 31 == k (base 32-aligned)
                        if (kcl < MAXDET) list[kcl] = i;
                        kcl++; add++;
                    }
                }
                kept |= newBits;
            }
            kc += __shfl_sync(0xFFFFFFFFu, add, wg);
            if (kc >= MAXDET) break;           // only first 100 kept are observable
#pragma unroll
            for (int k = 0; k < 32; ++k) mA[k] = mB[k];
        }
        __syncwarp();

        // write all MAXDET rows (zeros beyond K) — replaces a memset launch
        int K = kc < MAXDET ? kc : MAXDET;
        for (int s = l; s < MAXDET; s += 32) {
            float v0 = 0.f, v1 = 0.f, v2 = 0.f, v3 = 0.f, v4 = 0.f, v5 = 0.f;
            if (s < K) {
                int i = list[s];
                v0 = g_box[b][i][0]; v1 = g_box[b][i][1];
                v2 = g_box[b][i][2]; v3 = g_box[b][i][3];
                v4 = g_sc[b][i];     v5 = g_cf[b][i];
            }
            float* o = out + ((size_t)(b * MAXDET + s)) * 6;
            o[0] = v0; o[1] = v1; o[2] = v2; o[3] = v3; o[4] = v4; o[5] = v5;
        }
    }
}

// ---------------- launch ------------------------------------------------------
extern "C" void kernel_launch(void* const* d_in, const int* in_sizes, int n_in,
                              void* d_out, int out_size)
{
    const float* pred = (const float*)d_in[0];
    float* out = (float*)d_out;

    k_score <<<dim3(1050, BATCH), 96>>>(pred);
    k_select<<<BATCH, 1024>>>(pred);
    k_mask  <<<dim3(128, BATCH), 256>>>();
    k_scan  <<<BATCH, 256>>>(out);
}

// round 6
// speedup vs baseline: 3.5400x; 1.8127x over previous
#include <cuda_runtime.h>
#include <stdint.h>

#define BATCH  8
#define NANCH  100800
#define KPRE   1024
#define MAXDET 100

// ---------------- scratch (static device memory; no runtime allocation) ------
__device__ unsigned int        g_ukey[BATCH][NANCH];
__device__ unsigned char       g_cls [BATCH][NANCH];
__device__ unsigned int        g_hist[BATCH][2048];     // pass-A hist (self-zeroing)
__device__ unsigned long long  g_cand[BATCH][NANCH];    // pivot-bin candidates

// ---------------- kernel 1: coalesced score / argmax / key / histogram -------
__global__ void __launch_bounds__(96) k_score(const float* __restrict__ pred)
{
    __shared__ float tile[3][2720];        // 3 warps x 32 anchors x 85 floats

    int b = blockIdx.y;
    int w = threadIdx.x >> 5, l = threadIdx.x & 31;

    int base = blockIdx.x * 96 + w * 32;                 // 1050*96 == 100800 exactly
    const float4* p4 = (const float4*)(pred + ((size_t)b * NANCH + base) * 85);
    float4* t4 = (float4*)tile[w];
#pragma unroll
    for (int k = 0; k < 21; ++k) t4[k * 32 + l] = p4[k * 32 + l];
    if (l < 8) t4[672 + l] = p4[672 + l];                // 680 float4 = 2720 floats
    __syncwarp();                                        // per-warp tile, warp-local

    const float* row = &tile[w][l * 85];                 // stride 85: conflict-free
    float obj = row[4];

    // 4 independent strict-> chains merged by (value, lower index) ==
    // min-index-of-max == reference first-occurrence argmax
    float v0 = __fmul_rn(row[5], obj);     int i0 = 0;
    float v1 = __fmul_rn(row[6], obj);     int i1 = 1;
    float v2 = __fmul_rn(row[7], obj);     int i2 = 2;
    float v3 = __fmul_rn(row[8], obj);     int i3 = 3;
#pragma unroll
    for (int t = 1; t < 20; ++t) {
        int c = 4 * t;
        float a  = __fmul_rn(row[5 + c], obj);
        float bq = __fmul_rn(row[6 + c], obj);
        float cq = __fmul_rn(row[7 + c], obj);
        float dq = __fmul_rn(row[8 + c], obj);
        if (a  > v0) { v0 = a;  i0 = c;     }
        if (bq > v1) { v1 = bq; i1 = c + 1; }
        if (cq > v2) { v2 = cq; i2 = c + 2; }
        if (dq > v3) { v3 = dq; i3 = c + 3; }
    }
    float best = v0; int bi = i0;
    if (v1 > best || (v1 == best && i1 < bi)) { best = v1; bi = i1; }
    if (v2 > best || (v2 == best && i2 < bi)) { best = v2; bi = i2; }
    if (v3 > best || (v3 == best && i3 < bi)) { best = v3; bi = i3; }

    bool  valid = (obj > 0.25f) && (best > 0.25f);
    float sm    = valid ? best : -1.0f;
    int   sb    = __float_as_int(sm);
    unsigned u  = (unsigned)sb ^ ((sb < 0) ? 0xFFFFFFFFu : 0x80000000u);
    int n = base + l;
    g_ukey[b][n] = u;
    g_cls [b][n] = (unsigned char)bi;

    unsigned bin   = u >> 21;
    unsigned peers = __match_any_sync(0xFFFFFFFFu, bin);
    if ((int)l == __ffs(peers) - 1) atomicAdd(&g_hist[b][bin], (unsigned)__popc(peers));
}

// ---------------- kernel 2: select + sort + gather + lazy mask + scan --------
struct SmemB {
    unsigned hist[2048];
    unsigned long long selKey[KPRE];       // sort buffer 0
    unsigned long long sbuf1[KPRE];        // eqIdx storage + sort buffer 1
    float s0[KPRE], s1[KPRE], s2[KPRE], s3[KPRE], sar[KPRE];   // offset boxes
    float bx1[KPRE], by1[KPRE], bx2[KPRE], by2[KPRE];          // raw boxes
    float ssc[KPRE], scf[KPRE];
    unsigned smask[32][32];                // mask chunk: 32 rows x 32 words
    unsigned chunkSum[64];
    unsigned sres[2];
    int list[MAXDET];
    int cntGt, cntEq, cntCand, skc;
};

__device__ __forceinline__ void hist_add(unsigned* hist, unsigned bin, bool q)
{
    unsigned qm = __ballot_sync(0xFFFFFFFFu, q);
    if (q) {
        unsigned peers = __match_any_sync(qm, bin);
        int ld = __ffs(peers) - 1;
        if ((int)(threadIdx.x & 31) == ld) atomicAdd(&hist[bin], (unsigned)__popc(peers));
    }
}

__device__ __forceinline__ void find_bin(unsigned* hist, unsigned* chunkSum,
                                         int NB, unsigned K, unsigned* sres, int tid)
{
    int nch = NB >> 5;
    if (tid < nch) {
        unsigned s = 0;
        int base = tid << 5;
#pragma unroll 8
        for (int i = 0; i < 32; ++i) s += hist[base + i];
        chunkSum[tid] = s;
    }
    __syncthreads();
    if (tid == 0) {
        unsigned acc = 0;
        int c = nch - 1;
        for (;; --c) {
            unsigned cs = chunkSum[c];
            if (acc + cs >= K) break;
            acc += cs;
        }
        int bin = (c << 5) + 31;
        for (;; --bin) {
            unsigned hv = hist[bin];
            if (acc + hv >= K) break;
            acc += hv;
        }
        sres[0] = (unsigned)bin;
        sres[1] = acc;           // count strictly above bin
    }
    __syncthreads();
}

#define N4 (NANCH / 4)                     // 25200

__device__ __forceinline__ unsigned long long umaxll(unsigned long long a, unsigned long long b)
{ return a > b ? a : b; }
__device__ __forceinline__ unsigned long long uminll(unsigned long long a, unsigned long long b)
{ return a < b ? a : b; }

__global__ void __launch_bounds__(1024) k_nms(const float* __restrict__ pred,
                                              float* __restrict__ out)
{
    extern __shared__ unsigned char dyn[];
    SmemB* sm = (SmemB*)dyn;

    int b = blockIdx.x, tid = threadIdx.x;
    int l = tid & 31, warp = tid >> 5;
    const uint4* uk4 = (const uint4*)&g_ukey[b][0];
    unsigned long long* cand = &g_cand[b][0];
    int* eqIdx = (int*)sm->sbuf1;

    // ---- pass A: precomputed histogram (load + self-zero for next replay) ----
    sm->hist[tid] = g_hist[b][tid];
    sm->hist[tid + 1024] = g_hist[b][tid + 1024];
    __syncthreads();
    g_hist[b][tid] = 0; g_hist[b][tid + 1024] = 0;
    find_bin(sm->hist, sm->chunkSum, 2048, KPRE, sm->sres, tid);
    unsigned b1 = sm->sres[0], gt1 = sm->sres[1], K1 = KPRE - gt1;
    int C = (int)sm->hist[b1];             // pivot-bin candidate count (exact)
    if (tid == 0) { sm->cntGt = 0; sm->cntEq = 0; sm->cntCand = 0; }
    __syncthreads();

    // ---- single global scan: compact sure-winners + pivot-bin members ----
    for (int t = tid; t < N4; t += 1024) {
        uint4 q = uk4[t];
        unsigned uu[4] = {q.x, q.y, q.z, q.w};
#pragma unroll
        for (int j = 0; j < 4; ++j) {
            unsigned u = uu[j];
            unsigned hb = u >> 21;
            if (hb >= b1) {
                int n = 4 * t + j;
                unsigned long long key = ((unsigned long long)u << 32) | (unsigned)(~n);
                if (hb > b1) {
                    int p = atomicAdd(&sm->cntGt, 1);
                    sm->selKey[p] = key;
                } else {
                    int p = atomicAdd(&sm->cntCand, 1);
                    cand[p] = key;
                }
            }
        }
    }
    __syncthreads();

    // ---- pass B: mid 11 bits over candidates only ----
    sm->hist[tid] = 0; sm->hist[tid + 1024] = 0;
    __syncthreads();
    int iters = (C + 1023) >> 10;          // uniform across ALL threads
    for (int it = 0; it < iters; ++it) {
        int t = (it << 10) + tid;
        bool act = t < C;
        unsigned long long k = act ? cand[t] : 0ull;
        unsigned u = (unsigned)(k >> 32);
        hist_add(sm->hist, (u >> 10) & 2047u, act);
    }
    __syncthreads();
    find_bin(sm->hist, sm->chunkSum, 2048, K1, sm->sres, tid);
    unsigned b2 = sm->sres[0], gt2 = sm->sres[1], K2 = K1 - gt2;
    __syncthreads();

    // ---- pass C: low 10 bits over candidates matching b2 ----
    sm->hist[tid] = 0;
    __syncthreads();
    for (int it = 0; it < iters; ++it) {
        int t = (it << 10) + tid;
        bool act = t < C;
        unsigned long long k = act ? cand[t] : 0ull;
        unsigned u = (unsigned)(k >> 32);
        hist_add(sm->hist, u & 1023u, act && (((u >> 10) & 2047u) == b2));
    }
    __syncthreads();
    find_bin(sm->hist, sm->chunkSum, 1024, K2, sm->sres, tid);
    unsigned b3 = sm->sres[0], gt3 = sm->sres[1], K3 = K2 - gt3;
    unsigned ustar = (b1 << 21) | (b2 << 10) | b3;
    int totalGt = (int)(KPRE - K3);        // count strictly > pivot
    __syncthreads();

    // ---- pass D: partition candidates ----
    for (int t = tid; t < C; t += 1024) {
        unsigned long long k = cand[t];
        unsigned u = (unsigned)(k >> 32);
        if (u > ustar) {
            int p = atomicAdd(&sm->cntGt, 1);
            sm->selKey[p] = k;
        } else if (u == ustar) {
            int qq = atomicAdd(&sm->cntEq, 1);
            if (qq < 2048) eqIdx[qq] = (int)~((unsigned)(k & 0xFFFFFFFFull));
        }
    }
    __syncthreads();

    // ---- pass E: tie resolution by smallest index (jax top_k semantics) ----
    int E = sm->cntEq; if (E > 2048) E = 2048;
    for (int t = tid; t < E; t += 1024) {
        int my = eqIdx[t], r = 0;
        for (int s = 0; s < E; ++s) r += (eqIdx[s] < my);
        if (r < (int)K3)
            sm->selKey[totalGt + r] = ((unsigned long long)ustar << 32) | (unsigned)(~my);
    }
    __syncthreads();

    // ---- hybrid bitonic sort, descending (smem stages j>=32, shfl j<=16) ----
    unsigned long long key = sm->selKey[tid];
    int cur = 0;
#pragma unroll
    for (int k = 2; k <= 32; k <<= 1) {
        bool desc = ((tid & k) == 0);
#pragma unroll
        for (int j = k >> 1; j > 0; j >>= 1) {
            unsigned long long other = __shfl_xor_sync(0xFFFFFFFFu, key, j);
            bool lower = (tid & j) == 0;
            key = (lower == desc) ? umaxll(key, other) : uminll(key, other);
        }
    }
    __syncthreads();
    for (int k = 64; k <= KPRE; k <<= 1) {
        bool desc = ((tid & k) == 0);
        for (int j = k >> 1; j >= 32; j >>= 1) {
            unsigned long long* B = cur ? sm->sbuf1 : sm->selKey;
            B[tid] = key;
            __syncthreads();
            unsigned long long other = B[tid ^ j];
            bool lower = (tid & j) == 0;
            key = (lower == desc) ? umaxll(key, other) : uminll(key, other);
            cur ^= 1;
        }
#pragma unroll
        for (int j = 16; j > 0; j >>= 1) {
            unsigned long long other = __shfl_xor_sync(0xFFFFFFFFu, key, j);
            bool lower = (tid & j) == 0;
            key = (lower == desc) ? umaxll(key, other) : uminll(key, other);
        }
    }

    // ---- gather boxes / class / score into SMEM (bit-exact arithmetic) ----
    {
        unsigned n = ~((unsigned)(key & 0xFFFFFFFFull));
        unsigned u = (unsigned)(key >> 32);
        unsigned sb = (u & 0x80000000u) ? (u ^ 0x80000000u) : ~u;
        float sc = __int_as_float((int)sb);
        const float* p = pred + ((size_t)b * NANCH + n) * 85;
        float cx = __ldg(p), cy = __ldg(p + 1), w = __ldg(p + 2), h = __ldg(p + 3);
        float hw = __fmul_rn(w, 0.5f), hh = __fmul_rn(h, 0.5f);
        float x1 = __fsub_rn(cx, hw), y1 = __fsub_rn(cy, hh);
        float x2 = __fadd_rn(cx, hw), y2 = __fadd_rn(cy, hh);
        float cf = (float)(int)g_cls[b][n];
        float off = __fmul_rn(cf, 7680.0f);
        float o0 = __fadd_rn(x1, off), o1 = __fadd_rn(y1, off);
        float o2 = __fadd_rn(x2, off), o3 = __fadd_rn(y2, off);
        sm->bx1[tid] = x1; sm->by1[tid] = y1; sm->bx2[tid] = x2; sm->by2[tid] = y2;
        sm->s0[tid] = o0;  sm->s1[tid] = o1;  sm->s2[tid] = o2;  sm->s3[tid] = o3;
        sm->sar[tid] = __fmul_rn(__fsub_rn(o2, o0), __fsub_rn(o3, o1));
        sm->ssc[tid] = sc;
        sm->scf[tid] = cf;
        if (tid == 0) sm->skc = 0;
    }
    // V = valid count (scores sorted desc -> valid == prefix)
    int V = __syncthreads_count(sm->ssc[tid] > 0.0f);

    // ---- lazy mask + greedy scan, 32 rows per chunk, early exit at 100 ----
    unsigned kept = 0;                     // warp0: lane l owns rows [32l, 32l+32)
    int kc = 0;
    for (int c = 0; c < 32; ++c) {
        // build mask words for rows [32c, 32c+32): warp k -> row, ballot per word
        {
            int i = (c << 5) + warp;
            float a0 = sm->s0[i], a1 = sm->s1[i], a2 = sm->s2[i], a3 = sm->s3[i];
            float aa = sm->sar[i];
            for (int t = 0; t <= c; ++t) {
                int j = (t << 5) + l;
                bool bit = false;
                if (j < i) {
                    float xx1 = fmaxf(a0, sm->s0[j]);
                    float yy1 = fmaxf(a1, sm->s1[j]);
                    float xx2 = fminf(a2, sm->s2[j]);
                    float yy2 = fminf(a3, sm->s3[j]);
                    float ww = fmaxf(__fsub_rn(xx2, xx1), 0.0f);
                    float hh = fmaxf(__fsub_rn(yy2, yy1), 0.0f);
                    float inter = __fmul_rn(ww, hh);
                    float uni = __fsub_rn(__fadd_rn(aa, sm->sar[j]), inter);
                    float iou = __fdiv_rn(inter, __fadd_rn(uni, 1e-7f));
                    bit = iou > 0.45f;
                }
                unsigned word = __ballot_sync(0xFFFFFFFFu, bit);
                if (l == 0) sm->smask[warp][t] = word;
            }
        }
        __syncthreads();

        if (tid < 32) {                    // warp 0: scan this chunk
            unsigned mA[32];
#pragma unroll
            for (int k = 0; k < 32; ++k) mA[k] = (l <= c) ? sm->smask[k][l] : 0u;
            unsigned hv = 0;
#pragma unroll
            for (int k = 0; k < 32; ++k) hv |= ((mA[k] & kept) ? 1u : 0u) << k;
            unsigned grpHit = __reduce_or_sync(0xFFFFFFFFu, hv);
            int add = 0;
            if (l == c) {                  // word c = in-group bits
                unsigned newBits = 0;
                int kcl = kc;
#pragma unroll
                for (int k = 0; k < 32; ++k) {
                    int i = (c << 5) + k;
                    bool sup = ((grpHit >> k) & 1u) != 0u || (mA[k] & newBits) != 0u;
                    if (i < V && !sup) {
                        newBits |= 1u << k;
                        if (kcl < MAXDET) sm->list[kcl] = i;
                        kcl++; add++;
                    }
                }
                kept |= newBits;
            }
            kc += __shfl_sync(0xFFFFFFFFu, add, c);
            if (l == 0) sm->skc = kc;
        }
        __syncthreads();
        if (sm->skc >= MAXDET) break;      // only first 100 kept are observable
        if (((c + 1) << 5) >= V) break;    // remaining rows all invalid
    }

    // ---- output (zeros beyond K; replaces memset) ----
    int K = sm->skc; if (K > MAXDET) K = MAXDET;
    for (int s = tid; s < MAXDET; s += 1024) {
        float v0 = 0.f, v1 = 0.f, v2 = 0.f, v3 = 0.f, v4 = 0.f, v5 = 0.f;
        if (s < K) {
            int i = sm->list[s];
            v0 = sm->bx1[i]; v1 = sm->by1[i]; v2 = sm->bx2[i]; v3 = sm->by2[i];
            v4 = sm->ssc[i]; v5 = sm->scf[i];
        }
        float* o = out + ((size_t)(b * MAXDET + s)) * 6;
        o[0] = v0; o[1] = v1; o[2] = v2; o[3] = v3; o[4] = v4; o[5] = v5;
    }
}

// ---------------- launch ------------------------------------------------------
extern "C" void kernel_launch(void* const* d_in, const int* in_sizes, int n_in,
                              void* d_out, int out_size)
{
    const float* pred = (const float*)d_in[0];
    float* out = (float*)d_out;

    static int smem_set = 0;
    if (!smem_set) {
        cudaFuncSetAttribute(k_nms, cudaFuncAttributeMaxDynamicSharedMemorySize,
                             (int)sizeof(SmemB));
        smem_set = 1;
    }

    k_score<<<dim3(1050, BATCH), 96>>>(pred);
    k_nms  <<<BATCH, 1024, sizeof(SmemB)>>>(pred, out);
}